// round 6
// baseline (speedup 1.0000x reference)
#include <cuda_runtime.h>

#define FFT_M    4096   // complex FFT size (= d/2)
#define NREAL    8192   // sketch / output dim d
#define NTHREADS 512
#define IMG_DIM  2048
#define TXT_DIM  768
#define TWO_PI   6.2831853071795864f

// Padded shared-memory indexing: one extra float2 every 32 float2 (256B).
#define PIDX(i)  ((i) + ((i) >> 5))            // float2 index -> padded float2 index
#define RIDX(i)  ((i) + (((i) >> 6) << 1))     // float  index -> padded float  index
#define PADDED   (FFT_M + (FFT_M >> 5))        // 4224 float2 per buffer

__device__ __forceinline__ float2 cadd(float2 a, float2 b){ return make_float2(a.x+b.x, a.y+b.y); }
__device__ __forceinline__ float2 csub(float2 a, float2 b){ return make_float2(a.x-b.x, a.y-b.y); }
__device__ __forceinline__ float2 cmul(float2 a, float2 b){
    return make_float2(fmaf(a.x, b.x, -a.y*b.y), fmaf(a.x, b.y, a.y*b.x));
}

// In-register 8-point DFT, outputs in natural k order. DIR=-1 fwd, +1 inv.
template<int DIR>
__device__ __forceinline__ void dft8(float2 v[8]) {
    const float c8 = 0.70710678118654752f;
    float2 e0, e1, e2, e3, o0, o1, o2, o3;
    {
        float2 t0 = cadd(v[0], v[4]), t1 = csub(v[0], v[4]);
        float2 t2 = cadd(v[2], v[6]), t3 = csub(v[2], v[6]);
        float2 jt3 = (DIR < 0) ? make_float2(t3.y, -t3.x) : make_float2(-t3.y, t3.x);
        e0 = cadd(t0, t2); e2 = csub(t0, t2);
        e1 = cadd(t1, jt3); e3 = csub(t1, jt3);
    }
    {
        float2 t0 = cadd(v[1], v[5]), t1 = csub(v[1], v[5]);
        float2 t2 = cadd(v[3], v[7]), t3 = csub(v[3], v[7]);
        float2 jt3 = (DIR < 0) ? make_float2(t3.y, -t3.x) : make_float2(-t3.y, t3.x);
        o0 = cadd(t0, t2); o2 = csub(t0, t2);
        o1 = cadd(t1, jt3); o3 = csub(t1, jt3);
    }
    float2 u1 = (DIR < 0) ? make_float2(c8*(o1.x + o1.y), c8*(o1.y - o1.x))
                          : make_float2(c8*(o1.x - o1.y), c8*(o1.x + o1.y));
    float2 u2 = (DIR < 0) ? make_float2(o2.y, -o2.x)
                          : make_float2(-o2.y, o2.x);
    float2 u3 = (DIR < 0) ? make_float2(c8*(o3.y - o3.x), -c8*(o3.x + o3.y))
                          : make_float2(-c8*(o3.x + o3.y), c8*(o3.x - o3.y));
    v[0] = cadd(e0, o0); v[4] = csub(e0, o0);
    v[1] = cadd(e1, u1); v[5] = csub(e1, u1);
    v[2] = cadd(e2, u2); v[6] = csub(e2, u2);
    v[3] = cadd(e3, u3); v[7] = csub(e3, u3);
}

// 8x8 transpose across the 8 lanes of a group (lanes l..l+7 within warp).
// After: lane p slot s = old lane s slot p. All register indices compile-time.
__device__ __forceinline__ void xorT(float2 v[8], int lane) {
    #pragma unroll
    for (int m = 1; m <= 4; m <<= 1) {
        const bool hi = (lane & m) != 0;
        #pragma unroll
        for (int j0 = 0; j0 < 8; j0++) {
            if (j0 & m) continue;
            const int j1 = j0 | m;
            float sx = hi ? v[j0].x : v[j1].x;
            float sy = hi ? v[j0].y : v[j1].y;
            float gx = __shfl_xor_sync(0xffffffffu, sx, m);
            float gy = __shfl_xor_sync(0xffffffffu, sy, m);
            if (hi) { v[j0].x = gx; v[j0].y = gy; }
            else    { v[j1].x = gx; v[j1].y = gy; }
        }
    }
}

// One phase of the four-step 4096 FFT: a 64-point FFT done by an 8-thread
// group, data held in registers. Thread p loads z[8a+p] (a=0..7), two radix-8
// stages with inner twiddle W64^{rp} and an 8x8 shuffle transpose between.
// Output: slot q holds Y[8q+p], optionally multiplied by the outer twiddle
// W4096^{DIR*(8q+p)*lineIdx}, stored to baseOut + (8q+p)*esOut.
template<int DIR, bool OUTER>
__device__ __forceinline__ void fft64_line(
    const float2* __restrict__ in, float2* __restrict__ out,
    int baseIn, int esIn, int baseOut, int esOut,
    int p, int lineIdx, int lane)
{
    float2 v[8];
    #pragma unroll
    for (int a = 0; a < 8; a++)
        v[a] = in[PIDX(baseIn + (8*a + p) * esIn)];

    dft8<DIR>(v);                         // stage 1 (over a)
    {                                     // inner twiddle W64^{DIR * r * p}
        float s, c;
        __sincosf((float)DIR * (TWO_PI/64.0f) * (float)p, &s, &c);
        float2 w = make_float2(c, s);
        float2 wr = w;
        v[1] = cmul(v[1], wr);
        #pragma unroll
        for (int r = 2; r < 8; r++) { wr = cmul(wr, w); v[r] = cmul(v[r], wr); }
    }
    xorT(v, lane);                        // 8x8 transpose among group lanes
    dft8<DIR>(v);                         // stage 2 (over b)

    if (OUTER) {                          // W4096^{DIR*(8q+p)*lineIdx}
        float s0, c0, ss, cs;
        __sincosf((float)DIR * (TWO_PI/4096.0f) * (float)(p * lineIdx), &s0, &c0);
        __sincosf((float)DIR * (TWO_PI/512.0f)  * (float)lineIdx, &ss, &cs);
        float2 wq = make_float2(c0, s0);
        float2 st = make_float2(cs, ss);
        v[0] = cmul(v[0], wq);
        #pragma unroll
        for (int q = 1; q < 8; q++) { wq = cmul(wq, st); v[q] = cmul(v[q], wq); }
    }
    #pragma unroll
    for (int q = 0; q < 8; q++)
        out[PIDX(baseOut + (8*q + p) * esOut)] = v[q];
}

__global__ void __launch_bounds__(NTHREADS, 2)
bilinear_fusion_kernel(
    const float* __restrict__ img,  const float* __restrict__ txt,
    const int*   __restrict__ h1,   const int*   __restrict__ h2,
    const float* __restrict__ s1,   const float* __restrict__ s2,
    const float* __restrict__ gamma,const float* __restrict__ beta,
    float* __restrict__ out)
{
    extern __shared__ float2 sm[];
    float2* A = sm;               // sketch1 -> X1
    float2* B = sm +   PADDED;    // scratch -> ZY -> y
    float2* C = sm + 2*PADDED;    // sketch2 -> X2
    __shared__ float rs[16], rq[16];

    const int b    = blockIdx.x;
    const int tid  = threadIdx.x;
    const int lane = tid & 31;
    const int p    = tid & 7;     // lane-in-group
    const int G    = tid >> 3;    // group = line index (0..63)

    // ---- count sketches (scatter-add into smem, natural layout) ----
    float* rA = (float*)A;
    float* rC = (float*)C;
    for (int i = tid; i < 2 * PADDED; i += NTHREADS) { rA[i] = 0.0f; rC[i] = 0.0f; }
    __syncthreads();

    const float* irow = img + (size_t)b * IMG_DIM;
    for (int i = tid; i < IMG_DIM; i += NTHREADS)
        atomicAdd(&rA[RIDX(h1[i])], irow[i] * s1[i]);
    const float* trow = txt + (size_t)b * TXT_DIM;
    for (int i = tid; i < TXT_DIM; i += NTHREADS)
        atomicAdd(&rC[RIDX(h2[i])], trow[i] * s2[i]);
    __syncthreads();

    // ---- forward FFT of sketch1: A -(cols+twiddle)-> B -(rows)-> A (natural) ----
    fft64_line<-1, true >(A, B, G,      64, G, 64, p, G, lane);
    __syncthreads();
    fft64_line<-1, false>(B, A, G * 64,  1, G, 64, p, 0, lane);
    __syncthreads();
    // ---- forward FFT of sketch2: C -> B -> C (natural) ----
    fft64_line<-1, true >(C, B, G,      64, G, 64, p, G, lane);
    __syncthreads();
    fft64_line<-1, false>(B, C, G * 64,  1, G, 64, p, 0, lane);
    __syncthreads();

    // ---- unpack rFFTs, multiply spectra, repack; write ZY digit-swapped ----
    const float scale = 1.0f / (float)FFT_M;
    for (int k = tid; k <= FFT_M/2; k += NTHREADS) {
        int mk = (FFT_M - k) & (FFT_M - 1);
        float2 z1k = A[PIDX(k)],  z1m = A[PIDX(mk)];
        float2 z2k = C[PIDX(k)],  z2m = C[PIDX(mk)];
        float sa, ca;
        __sincosf(-TWO_PI * (float)k / (float)NREAL, &sa, &ca);
        float2 w = make_float2(ca, sa);            // W_N^k

        float2 E1  = make_float2(0.5f*(z1k.x + z1m.x), 0.5f*(z1k.y - z1m.y));
        float2 O1t = make_float2(0.5f*(z1k.x - z1m.x), 0.5f*(z1k.y + z1m.y));
        float2 O1  = make_float2(O1t.y, -O1t.x);   // -i * O1t
        float2 WO1 = cmul(w, O1);
        float2 P1  = cadd(E1, WO1);
        float2 Q1  = csub(E1, WO1);

        float2 E2  = make_float2(0.5f*(z2k.x + z2m.x), 0.5f*(z2k.y - z2m.y));
        float2 O2t = make_float2(0.5f*(z2k.x - z2m.x), 0.5f*(z2k.y + z2m.y));
        float2 O2  = make_float2(O2t.y, -O2t.x);
        float2 WO2 = cmul(w, O2);
        float2 P2  = cadd(E2, WO2);
        float2 Q2  = csub(E2, WO2);

        float2 Yk  = cmul(P1, P2);
        float2 Ymc = cmul(Q1, Q2);                 // conj(Y[M-k])
        float2 G2  = make_float2(0.5f*(Yk.x + Ymc.x), 0.5f*(Yk.y + Ymc.y));
        float2 Hm  = make_float2(0.5f*(Yk.x - Ymc.x), 0.5f*(Yk.y - Ymc.y));
        float2 H   = cmul(make_float2(w.x, -w.y), Hm);

        // digit-swapped position: ZY[k] -> [(k mod 64)*64 + k/64]
        int sk = ((k & 63) << 6) | (k >> 6);
        B[PIDX(sk)] = make_float2(scale*(G2.x - H.y), scale*(G2.y + H.x));
        if (k != 0 && k != FFT_M/2) {
            int smk = ((mk & 63) << 6) | (mk >> 6);
            B[PIDX(smk)] = make_float2(scale*(G2.x + H.y), scale*(H.x - G2.y));
        }
    }
    __syncthreads();

    // ---- inverse FFT: B(swapped) -(rows+twiddle)-> A -(cols)-> B (natural) ----
    fft64_line<1, true >(B, A, G * 64, 1, G * 64, 1, p, G, lane);
    __syncthreads();
    fft64_line<1, false>(A, B, G,     64, G,     64, p, 0, lane);
    __syncthreads();

    // ---- LayerNorm over the 8192 reals ----
    float sum = 0.0f, sq = 0.0f;
    for (int n = tid; n < FFT_M; n += NTHREADS) {
        float2 v = B[PIDX(n)];
        sum += v.x + v.y;
        sq = fmaf(v.x, v.x, sq);
        sq = fmaf(v.y, v.y, sq);
    }
    #pragma unroll
    for (int o = 16; o; o >>= 1) {
        sum += __shfl_down_sync(0xffffffffu, sum, o);
        sq  += __shfl_down_sync(0xffffffffu, sq,  o);
    }
    const int wid = tid >> 5, lid = tid & 31;
    if (lid == 0) { rs[wid] = sum; rq[wid] = sq; }
    __syncthreads();
    if (wid == 0) {
        sum = (lid < 16) ? rs[lid] : 0.0f;
        sq  = (lid < 16) ? rq[lid] : 0.0f;
        #pragma unroll
        for (int o = 8; o; o >>= 1) {
            sum += __shfl_down_sync(0xffffffffu, sum, o);
            sq  += __shfl_down_sync(0xffffffffu, sq,  o);
        }
        if (lid == 0) { rs[0] = sum; rq[0] = sq; }
    }
    __syncthreads();
    const float mean = rs[0] * (1.0f / (float)NREAL);
    const float var  = rq[0] * (1.0f / (float)NREAL) - mean * mean;
    const float inv  = rsqrtf(var + 1e-5f);

    float2* orow = (float2*)(out + (size_t)b * NREAL);
    const float2* g2 = (const float2*)gamma;
    const float2* b2 = (const float2*)beta;
    for (int n = tid; n < FFT_M; n += NTHREADS) {
        float2 v  = B[PIDX(n)];
        float2 g  = g2[n];
        float2 be = b2[n];
        orow[n] = make_float2(fmaf((v.x - mean) * inv, g.x, be.x),
                              fmaf((v.y - mean) * inv, g.y, be.y));
    }
}

extern "C" void kernel_launch(void* const* d_in, const int* in_sizes, int n_in,
                              void* d_out, int out_size) {
    const float* img   = (const float*)d_in[0];
    const float* txt   = (const float*)d_in[1];
    const int*   h1    = (const int*)  d_in[2];
    const int*   h2    = (const int*)  d_in[3];
    const float* s1    = (const float*)d_in[4];
    const float* s2    = (const float*)d_in[5];
    const float* gamma = (const float*)d_in[6];
    const float* beta  = (const float*)d_in[7];
    float* out = (float*)d_out;

    const int batch = in_sizes[0] / IMG_DIM;
    const size_t smem = 3 * PADDED * sizeof(float2);   // ~99 KB
    cudaFuncSetAttribute(bilinear_fusion_kernel,
                         cudaFuncAttributeMaxDynamicSharedMemorySize, (int)smem);
    bilinear_fusion_kernel<<<batch, NTHREADS, smem>>>(
        img, txt, h1, h2, s1, s2, gamma, beta, out);
}